// round 2
// baseline (speedup 1.0000x reference)
#include <cuda_runtime.h>
#include <math.h>

// Shapes (fixed by the problem)
#define BWIN 256      // B_
#define NTOK 343      // N = 7*7*7
#define CH   384      // C
#define NH   12       // heads
#define HD   32       // head dim
#define KV2  768      // 2*C
#define NMASK 64      // nW
#define MROWS 87808   // BWIN*NTOK  (= 128*686)

// Scratch (device globals -- no cudaMalloc allowed)
__device__ float g_kv[BWIN * NTOK * KV2];     // kv projection output [b][n][768]
__device__ float g_attn[BWIN * NTOK * CH];    // attention output     [b][n][384]

// ---------------------------------------------------------------------------
// SGEMM: C[M,Nc] = (A (+A2)) [M,K] @ B[K,Nc] + bias[Nc]
// BM=128 BN=128 BK=8, TM=TN=8, 256 threads. Requires M%128==0, Nc%128==0, K%8==0.
// ---------------------------------------------------------------------------
template <bool ADD>
__global__ __launch_bounds__(256)
void sgemm128(const float* __restrict__ A, const float* __restrict__ A2,
              const float* __restrict__ B, const float* __restrict__ bias,
              float* __restrict__ C, int M, int Nc, int K)
{
    constexpr int BM = 128, BN = 128, BK = 8, TM = 8, TN = 8;
    __shared__ float As[BK * BM];   // transposed: As[k][m]
    __shared__ float Bs[BK * BN];   // Bs[k][n]

    const int cRow = blockIdx.y;
    const int cCol = blockIdx.x;
    const int tid  = threadIdx.x;
    const int tCol = tid % (BN / TN);   // 0..15
    const int tRow = tid / (BN / TN);   // 0..15

    const float* Ab  = A  + (size_t)cRow * BM * K;
    const float* A2b = ADD ? (A2 + (size_t)cRow * BM * K) : nullptr;
    const float* Bb  = B  + cCol * BN;
    float*       Cb  = C  + (size_t)cRow * BM * Nc + cCol * BN;

    const int aRow = tid >> 1;          // 0..127
    const int aCol = (tid & 1) * 4;     // 0 or 4
    const int bRow = tid >> 5;          // 0..7
    const int bCol = (tid & 31) * 4;    // 0..124

    float acc[TM][TN];
    #pragma unroll
    for (int i = 0; i < TM; i++)
        #pragma unroll
        for (int j = 0; j < TN; j++) acc[i][j] = 0.f;

    for (int k0 = 0; k0 < K; k0 += BK) {
        float4 av = *(const float4*)(Ab + (size_t)aRow * K + k0 + aCol);
        if (ADD) {
            float4 a2 = *(const float4*)(A2b + (size_t)aRow * K + k0 + aCol);
            av.x += a2.x; av.y += a2.y; av.z += a2.z; av.w += a2.w;
        }
        As[(aCol + 0) * BM + aRow] = av.x;
        As[(aCol + 1) * BM + aRow] = av.y;
        As[(aCol + 2) * BM + aRow] = av.z;
        As[(aCol + 3) * BM + aRow] = av.w;

        float4 bv = *(const float4*)(Bb + (size_t)(k0 + bRow) * Nc + bCol);
        *(float4*)(Bs + bRow * BN + bCol) = bv;

        __syncthreads();

        #pragma unroll
        for (int kk = 0; kk < BK; kk++) {
            float rM[TM], rN[TN];
            float4 m0 = *(const float4*)(&As[kk * BM + tRow * TM]);
            float4 m1 = *(const float4*)(&As[kk * BM + tRow * TM + 4]);
            rM[0]=m0.x; rM[1]=m0.y; rM[2]=m0.z; rM[3]=m0.w;
            rM[4]=m1.x; rM[5]=m1.y; rM[6]=m1.z; rM[7]=m1.w;
            float4 n0 = *(const float4*)(&Bs[kk * BN + tCol * TN]);
            float4 n1 = *(const float4*)(&Bs[kk * BN + tCol * TN + 4]);
            rN[0]=n0.x; rN[1]=n0.y; rN[2]=n0.z; rN[3]=n0.w;
            rN[4]=n1.x; rN[5]=n1.y; rN[6]=n1.z; rN[7]=n1.w;
            #pragma unroll
            for (int i = 0; i < TM; i++)
                #pragma unroll
                for (int j = 0; j < TN; j++)
                    acc[i][j] += rM[i] * rN[j];
        }
        __syncthreads();
    }

    // epilogue with bias
    #pragma unroll
    for (int i = 0; i < TM; i++) {
        float* crow = Cb + (size_t)(tRow * TM + i) * Nc + tCol * TN;
        const float* brow = bias + cCol * BN + tCol * TN;
        #pragma unroll
        for (int j = 0; j < TN; j += 4) {
            float4 o;
            o.x = acc[i][j + 0] + brow[j + 0];
            o.y = acc[i][j + 1] + brow[j + 1];
            o.z = acc[i][j + 2] + brow[j + 2];
            o.w = acc[i][j + 3] + brow[j + 3];
            *(float4*)(crow + j) = o;
        }
    }
}

// ---------------------------------------------------------------------------
// Fused window attention kernel: one CTA per (head, window-batch).
// K/V tiles + rel-pos-bias table + position codes in SMEM.
// q normalized+scaled in registers; online softmax; writes [b][n][h*32+i].
// ---------------------------------------------------------------------------
__global__ __launch_bounds__(352, 2)
void attn_kernel(const float* __restrict__ xup,
                 const float* __restrict__ mask,
                 const float* __restrict__ lscale,
                 const float* __restrict__ rpb)
{
    const int h = blockIdx.x;
    const int b = blockIdx.y;

    extern __shared__ float sm[];
    float* kn   = sm;                 // 343*32 normalized K
    float* vv   = sm + NTOK * HD;     // 343*32 V
    float* btab = sm + 2 * NTOK * HD; // 412 floats (409 used)
    int*   code = (int*)(sm + 2 * NTOK * HD + 412); // 343 ints

    const float* kvb = g_kv + (size_t)b * NTOK * KV2;

    // Load K (normalize) and V into SMEM; compute position codes.
    for (int r = threadIdx.x; r < NTOK; r += 352) {
        const float4* ks = (const float4*)(kvb + (size_t)r * KV2 + h * HD);
        const float4* vs = (const float4*)(kvb + (size_t)r * KV2 + CH + h * HD);
        float4 kr[8];
        float ss = 0.f;
        #pragma unroll
        for (int j = 0; j < 8; j++) {
            kr[j] = ks[j];
            ss += kr[j].x * kr[j].x + kr[j].y * kr[j].y
                + kr[j].z * kr[j].z + kr[j].w * kr[j].w;
        }
        float inv = 1.f / fmaxf(sqrtf(ss), 1e-12f);
        float4* kd = (float4*)(kn + r * HD);
        float4* vd = (float4*)(vv + r * HD);
        #pragma unroll
        for (int j = 0; j < 8; j++) {
            float4 x = kr[j];
            x.x *= inv; x.y *= inv; x.z *= inv; x.w *= inv;
            kd[j] = x;
            vd[j] = vs[j];
        }
        int s = r / 49;
        int rem = r - s * 49;
        int hh = rem / 7;
        int w = rem - hh * 7;
        code[r] = s * 20 + hh * 13 + w;   // idx(n,m) = code[n]-code[m]+204 in [0,408]
    }
    // Bias table slice for this head (only indices 0..408 are reachable)
    for (int i = threadIdx.x; i < 409; i += 352)
        btab[i] = rpb[(size_t)i * NH + h];
    __syncthreads();

    const int n = threadIdx.x;
    if (n >= NTOK) return;

    // Load q row, fold normalization + logit scale into it.
    float4 q[8];
    {
        const float4* qs = (const float4*)(xup + ((size_t)b * NTOK + n) * CH + h * HD);
        float ss = 0.f;
        #pragma unroll
        for (int j = 0; j < 8; j++) {
            q[j] = qs[j];
            ss += q[j].x * q[j].x + q[j].y * q[j].y + q[j].z * q[j].z + q[j].w * q[j].w;
        }
        float sc = __expf(fminf(lscale[h], 4.6051702f));   // min(logit_scale, ln 100)
        float qm = sc / fmaxf(sqrtf(ss), 1e-12f);
        #pragma unroll
        for (int j = 0; j < 8; j++) {
            q[j].x *= qm; q[j].y *= qm; q[j].z *= qm; q[j].w *= qm;
        }
    }

    const float* mrow = mask + ((size_t)(b & 63) * NTOK + n) * NTOK;
    const int cn = code[n] + 204;

    float Mx = -1e30f, L = 0.f;
    float4 acc[8];
    #pragma unroll
    for (int j = 0; j < 8; j++) acc[j] = make_float4(0.f, 0.f, 0.f, 0.f);

    for (int m = 0; m < NTOK; m++) {
        const float4* kr = (const float4*)(kn + m * HD);
        float d0 = 0.f, d1 = 0.f, d2 = 0.f, d3 = 0.f;
        #pragma unroll
        for (int j = 0; j < 8; j += 4) {
            float4 k0 = kr[j], k1 = kr[j + 1], k2 = kr[j + 2], k3 = kr[j + 3];
            d0 += q[j].x   * k0.x + q[j].y   * k0.y + q[j].z   * k0.z + q[j].w   * k0.w;
            d1 += q[j+1].x * k1.x + q[j+1].y * k1.y + q[j+1].z * k1.z + q[j+1].w * k1.w;
            d2 += q[j+2].x * k2.x + q[j+2].y * k2.y + q[j+2].z * k2.z + q[j+2].w * k2.w;
            d3 += q[j+3].x * k3.x + q[j+3].y * k3.y + q[j+3].z * k3.z + q[j+3].w * k3.w;
        }
        float s = (d0 + d1) + (d2 + d3);
        s += btab[cn - code[m]] + __ldg(mrow + m);

        float Mn = fmaxf(Mx, s);
        float p = __expf(s - Mn);
        if (Mn > Mx) {
            float c = __expf(Mx - Mn);
            L = L * c + p;
            #pragma unroll
            for (int j = 0; j < 8; j++) {
                acc[j].x *= c; acc[j].y *= c; acc[j].z *= c; acc[j].w *= c;
            }
            Mx = Mn;
        } else {
            L += p;
        }
        const float4* vr = (const float4*)(vv + m * HD);
        #pragma unroll
        for (int j = 0; j < 8; j++) {
            float4 vx = vr[j];
            acc[j].x += p * vx.x; acc[j].y += p * vx.y;
            acc[j].z += p * vx.z; acc[j].w += p * vx.w;
        }
    }

    float invL = 1.f / L;
    float4* od = (float4*)(g_attn + ((size_t)b * NTOK + n) * CH + h * HD);
    #pragma unroll
    for (int j = 0; j < 8; j++) {
        acc[j].x *= invL; acc[j].y *= invL; acc[j].z *= invL; acc[j].w *= invL;
        od[j] = acc[j];
    }
}

// ---------------------------------------------------------------------------
// Launch
// ---------------------------------------------------------------------------
extern "C" void kernel_launch(void* const* d_in, const int* in_sizes, int n_in,
                              void* d_out, int out_size)
{
    const float* skip   = (const float*)d_in[0];
    const float* x_up   = (const float*)d_in[1];
    const float* pos    = (const float*)d_in[2];
    const float* mask   = (const float*)d_in[3];
    const float* kv_w   = (const float*)d_in[4];
    const float* kv_b   = (const float*)d_in[5];
    const float* proj_w = (const float*)d_in[6];
    const float* proj_b = (const float*)d_in[7];
    const float* lsc    = (const float*)d_in[8];
    const float* rpb    = (const float*)d_in[9];
    float* out = (float*)d_out;

    void* kvp = nullptr;
    void* atp = nullptr;
    cudaGetSymbolAddress(&kvp, g_kv);
    cudaGetSymbolAddress(&atp, g_attn);
    float* kv_scratch   = (float*)kvp;
    float* attn_scratch = (float*)atp;

    const int smem_attn = (2 * NTOK * HD + 412) * 4 + NTOK * 4;  // ~90.8 KB
    cudaFuncSetAttribute(attn_kernel, cudaFuncAttributeMaxDynamicSharedMemorySize, smem_attn);

    // 1) KV projection: [87808,384] x [384,768] + bias
    sgemm128<false><<<dim3(KV2 / 128, MROWS / 128), 256>>>(
        skip, nullptr, kv_w, kv_b, kv_scratch, MROWS, KV2, CH);

    // 2) Fused cosine window attention (per head x window-batch)
    attn_kernel<<<dim3(NH, BWIN), 352, smem_attn>>>(x_up, mask, lsc, rpb);

    // 3) Output projection with fused (+pos_embed): [87808,384] x [384,384] + bias
    sgemm128<true><<<dim3(CH / 128, MROWS / 128), 256>>>(
        attn_scratch, pos, proj_w, proj_b, out, MROWS, CH, CH);
}